// round 6
// baseline (speedup 1.0000x reference)
#include <cuda_runtime.h>
#include <math.h>

#define HH 96
#define WW 96
#define HWc 9216         // 96*96
#define BB 4
#define NN 36864         // BB*HWc

// ---------------- scratch (static device allocations; no cudaMalloc) ----------
__device__ float g_col[169869312];   // max 9*512 x 36864  (layer 3)  ~680 MB
__device__ float g_wA[1179648];      // max O*9*C = 256*4608
__device__ float g_y1[2359296];      // 4*64*9216
__device__ float g_y2[18874368];     // 4*512*9216
__device__ float g_py[331776];       // 4*9*9216
__device__ float g_px[331776];
__device__ float g_mask[331776];

// ---------------- 1) offset conv: om = conv3x3(x, ow) + ob → py/px/mask -------
// block = 128 threads = 16x8 pixel tile; grid = (6, 12, B)
template<int CB>
__global__ void offset_conv_kernel(const float* __restrict__ x,
                                   const float* __restrict__ ow,
                                   const float* __restrict__ ob, int C)
{
    __shared__ float ws[CB * 9 * 27];
    const int tid = threadIdx.x;
    const int tx = tid & 15, ty = tid >> 4;
    const int w0 = blockIdx.x * 16 + tx;
    const int h0 = blockIdx.y * 8 + ty;
    const int b  = blockIdx.z;

    float acc[27];
#pragma unroll
    for (int i = 0; i < 27; i++) acc[i] = 0.f;

    for (int c0 = 0; c0 < C; c0 += CB) {
        __syncthreads();
        for (int i = tid; i < CB * 9 * 27; i += 128) {
            int oc  = i % 27;
            int r   = i / 27;
            int tap = r % 9;
            int cc  = r / 9;
            ws[i] = ow[((size_t)oc * C + c0 + cc) * 9 + tap];
        }
        __syncthreads();

        for (int cc = 0; cc < CB; cc++) {
            const float* xp = x + ((size_t)b * C + c0 + cc) * HWc;
            float xv[9];
#pragma unroll
            for (int dy = 0; dy < 3; dy++)
#pragma unroll
                for (int dx = 0; dx < 3; dx++) {
                    int yy = h0 + dy - 1, xx = w0 + dx - 1;
                    bool v = (yy >= 0) & (yy < HH) & (xx >= 0) & (xx < WW);
                    xv[dy * 3 + dx] = v ? xp[yy * WW + xx] : 0.f;
                }
#pragma unroll
            for (int tap = 0; tap < 9; tap++) {
                const float* wr = &ws[(cc * 9 + tap) * 27];
                float xvv = xv[tap];
#pragma unroll
                for (int oc = 0; oc < 27; oc++) acc[oc] += xvv * wr[oc];
            }
        }
    }

#pragma unroll
    for (int i = 0; i < 27; i++) acc[i] += ob[i];

    const int pix = h0 * WW + w0;
#pragma unroll
    for (int k = 0; k < 9; k++) {
        float oy = acc[2 * k];
        float ox = acc[2 * k + 1];
        float m  = 1.f / (1.f + __expf(-acc[18 + k]));
        int ky = k / 3, kx = k % 3;
        int idx = (b * 9 + k) * HWc + pix;
        g_py[idx]   = (float)(h0 + ky - 1) + oy;
        g_px[idx]   = (float)(w0 + kx - 1) + ox;
        g_mask[idx] = m;
    }
}

// ---------------- 2) deformable im2col gather → g_col[9C, NN] ----------------
__global__ void gather_kernel(const float* __restrict__ x, int C)
{
    int idx = blockIdx.x * blockDim.x + threadIdx.x;  // over BB*9*HWc
    if (idx >= BB * 9 * HWc) return;
    int hw = idx % HWc;
    int bk = idx / HWc;
    int k  = bk % 9;
    int b  = bk / 9;

    float pyv = g_py[idx], pxv = g_px[idx], m = g_mask[idx];
    float y0f = floorf(pyv), x0f = floorf(pxv);
    float wy = pyv - y0f, wx = pxv - x0f;
    int y0 = (int)y0f, x0 = (int)x0f;
    int y1 = y0 + 1, x1 = x0 + 1;
    float vy0 = (y0 >= 0 && y0 < HH) ? 1.f : 0.f;
    float vy1 = (y1 >= 0 && y1 < HH) ? 1.f : 0.f;
    float vx0 = (x0 >= 0 && x0 < WW) ? 1.f : 0.f;
    float vx1 = (x1 >= 0 && x1 < WW) ? 1.f : 0.f;
    float w00 = (1.f - wy) * (1.f - wx) * m * vy0 * vx0;
    float w01 = (1.f - wy) * wx         * m * vy0 * vx1;
    float w10 = wy         * (1.f - wx) * m * vy1 * vx0;
    float w11 = wy         * wx         * m * vy1 * vx1;

    int cy0 = min(max(y0, 0), HH - 1), cy1 = min(max(y1, 0), HH - 1);
    int cx0 = min(max(x0, 0), WW - 1), cx1 = min(max(x1, 0), WW - 1);
    int o00 = cy0 * WW + cx0, o01 = cy0 * WW + cx1;
    int o10 = cy1 * WW + cx0, o11 = cy1 * WW + cx1;

    const float* base = x + (size_t)b * C * HWc;
    size_t outIdx = (size_t)k * C * NN + (size_t)b * HWc + hw;
#pragma unroll 4
    for (int c = 0; c < C; c++) {
        const float* p = base + (size_t)c * HWc;
        float v = w00 * p[o00] + w01 * p[o01] + w10 * p[o10] + w11 * p[o11];
        g_col[outIdx] = v;
        outIdx += NN;
    }
}

// ---------------- 3a) weight repack: wA[o][k*C + c] = w[o][c][k] -------------
__global__ void repack_w_kernel(const float* __restrict__ w, int O, int C)
{
    int idx = blockIdx.x * blockDim.x + threadIdx.x;
    if (idx >= O * C * 9) return;
    int tap = idx % 9;
    int c   = (idx / 9) % C;
    int o   = idx / (9 * C);
    g_wA[(size_t)o * 9 * C + tap * C + c] = w[idx];
}

// ---------------- 3b) SGEMM: out[o][n] = sum_kc wA[o][kc]*col[kc][n] ---------
// BN=128, BK=8, TM=TN=8; BM templated (64 or 128). N=36864 (divides 128),
// K = 9*C (divides 8), M = O (divides BM). Epilogue adds bias and scatters
// into [B, O, H, W] layout (n-tiles never straddle batch: HWc % 128 == 0).
template<int BM>
__global__ void sgemm_kernel(int K, const float* __restrict__ bias,
                             float* __restrict__ out, int O)
{
    const int BN = 128, BK = 8, TM = 8, TN = 8;
    const int THREADS = (BM / TM) * (BN / TN);
    __shared__ float As[BK * BM];
    __shared__ float Bs[BK * BN];
    const int tid  = threadIdx.x;
    const int tcol = tid % (BN / TN);
    const int trow = tid / (BN / TN);

    const float* A  = g_wA + (size_t)blockIdx.y * BM * K;
    const float* Bp = g_col + blockIdx.x * BN;

    float acc[TM][TN];
#pragma unroll
    for (int i = 0; i < TM; i++)
#pragma unroll
        for (int j = 0; j < TN; j++) acc[i][j] = 0.f;

    const int aRow = tid / 2;
    const int aCol = (tid & 1) * 4;
    const int aStride = THREADS / 2;
    const int bRow = tid / 32;
    const int bCol = (tid & 31) * 4;
    const int bStride = THREADS / 32;

    for (int k0 = 0; k0 < K; k0 += BK) {
#pragma unroll
        for (int r = aRow; r < BM; r += aStride) {
            float4 v = *(const float4*)(A + (size_t)r * K + k0 + aCol);
            As[(aCol + 0) * BM + r] = v.x;
            As[(aCol + 1) * BM + r] = v.y;
            As[(aCol + 2) * BM + r] = v.z;
            As[(aCol + 3) * BM + r] = v.w;
        }
#pragma unroll
        for (int r = bRow; r < BK; r += bStride) {
            *(float4*)(&Bs[r * BN + bCol]) =
                *(const float4*)(Bp + (size_t)(k0 + r) * NN + bCol);
        }
        __syncthreads();
#pragma unroll
        for (int kk = 0; kk < BK; kk++) {
            float regM[TM], regN[TN];
#pragma unroll
            for (int i = 0; i < TM; i++) regM[i] = As[kk * BM + trow * TM + i];
#pragma unroll
            for (int j = 0; j < TN; j++) regN[j] = Bs[kk * BN + tcol * TN + j];
#pragma unroll
            for (int i = 0; i < TM; i++)
#pragma unroll
                for (int j = 0; j < TN; j++)
                    acc[i][j] += regM[i] * regN[j];
        }
        __syncthreads();
    }

    const int nBase = blockIdx.x * BN + tcol * TN;
    const int b   = nBase / HWc;
    const int hw0 = nBase % HWc;
    const int mBase = blockIdx.y * BM + trow * TM;
#pragma unroll
    for (int i = 0; i < TM; i++) {
        int o = mBase + i;
        float bv = bias[o];
        float* op = out + ((size_t)b * O + o) * HWc + hw0;
#pragma unroll
        for (int j = 0; j < TN; j += 4) {
            float4 v;
            v.x = acc[i][j + 0] + bv;
            v.y = acc[i][j + 1] + bv;
            v.z = acc[i][j + 2] + bv;
            v.w = acc[i][j + 3] + bv;
            *(float4*)(op + j) = v;
        }
    }
}

// ---------------- host-side layer driver -------------------------------------
static void run_layer(const float* in, int C,
                      const float* ow, const float* obias,
                      const float* w, const float* bias, int O, float* out)
{
    dim3 gOff(WW / 16, HH / 8, BB);
    offset_conv_kernel<16><<<gOff, 128>>>(in, ow, obias, C);

    int nG = BB * 9 * HWc;
    gather_kernel<<<(nG + 255) / 256, 256>>>(in, C);

    int nW = O * C * 9;
    repack_w_kernel<<<(nW + 255) / 256, 256>>>(w, O, C);

    int K = 9 * C;
    if (O >= 128) {
        dim3 grid(NN / 128, O / 128);
        sgemm_kernel<128><<<grid, 256>>>(K, bias, out, O);
    } else {
        dim3 grid(NN / 128, O / 64);
        sgemm_kernel<64><<<grid, 128>>>(K, bias, out, O);
    }
}

extern "C" void kernel_launch(void* const* d_in, const int* in_sizes, int n_in,
                              void* d_out, int out_size)
{
    const float* x   = (const float*)d_in[0];
    const float* ow1 = (const float*)d_in[1];
    const float* ob1 = (const float*)d_in[2];
    const float* w1  = (const float*)d_in[3];
    const float* b1  = (const float*)d_in[4];
    const float* ow2 = (const float*)d_in[5];
    const float* ob2 = (const float*)d_in[6];
    const float* w2  = (const float*)d_in[7];
    const float* b2  = (const float*)d_in[8];
    const float* ow3 = (const float*)d_in[9];
    const float* ob3 = (const float*)d_in[10];
    const float* w3  = (const float*)d_in[11];
    const float* b3  = (const float*)d_in[12];
    float* out = (float*)d_out;

    float *y1 = nullptr, *y2 = nullptr;
    cudaGetSymbolAddress((void**)&y1, g_y1);
    cudaGetSymbolAddress((void**)&y2, g_y2);

    run_layer(x,   64, ow1, ob1, w1, b1,  64, y1);
    run_layer(y1,  64, ow2, ob2, w2, b2, 512, y2);
    run_layer(y2, 512, ow3, ob3, w3, b3, 256, out);
}